// round 6
// baseline (speedup 1.0000x reference)
#include <cuda_runtime.h>
#include <cstdint>

// ConcatenateMeanMax: out[b] = concat(bond_ft[b],
//                                     mean(atom_ft[src[2b]], atom_ft[src[2b+1]]),
//                                     max (atom_ft[src[2b]], atom_ft[src[2b+1]]))
// edge_dst = repeat(arange(N_BONDS), 2)  =>  segment b is exactly edges {2b, 2b+1}.
//
// R5: 256-bit loads (.v8.b32, sm_100+) with INLINE L2 eviction hints (ptxas
// accepts .L2::evict_last only on v8.b32/v4.b64 — per the R2 error message).
// Half-warp per bond: lanes 0-15 -> bond 2w, lanes 16-31 -> bond 2w+1, each
// lane owns 8 floats (32B). All 3 gathers/reads issued as independent 256-bit
// loads before compute -> no cross-bond store/load serialization (the R3/R4
// regression: regs=32 showed the compiler serialized the two do_bond calls,
// dropping DRAM% 84.4 -> 80.9).
//  - atom gathers : ld.global.nc.L2::evict_last.v8   (keep table resident)
//  - bond reads   : ld.global.nc.L2::evict_first.v8  (streaming)
//  - out stores   : st.global.cs.v4                  (streaming)

#define D 128

__device__ __forceinline__ void ld_v8_last(const float* p, float* r) {
    asm("ld.global.nc.L2::evict_last.v8.b32 {%0,%1,%2,%3,%4,%5,%6,%7}, [%8];"
        : "=f"(r[0]), "=f"(r[1]), "=f"(r[2]), "=f"(r[3]),
          "=f"(r[4]), "=f"(r[5]), "=f"(r[6]), "=f"(r[7])
        : "l"(p));
}

__device__ __forceinline__ void ld_v8_first(const float* p, float* r) {
    asm("ld.global.nc.L2::evict_first.v8.b32 {%0,%1,%2,%3,%4,%5,%6,%7}, [%8];"
        : "=f"(r[0]), "=f"(r[1]), "=f"(r[2]), "=f"(r[3]),
          "=f"(r[4]), "=f"(r[5]), "=f"(r[6]), "=f"(r[7])
        : "l"(p));
}

__device__ __forceinline__ void st_v4_cs(float* p, float a, float b, float c, float d) {
    asm volatile("st.global.cs.v4.f32 [%0], {%1,%2,%3,%4};"
                 :: "l"(p), "f"(a), "f"(b), "f"(c), "f"(d));
}

__global__ __launch_bounds__(256) void concat_mean_max_kernel(
    const float* __restrict__ atom_ft,
    const float* __restrict__ bond_ft,
    const int*   __restrict__ edge_src,
    float* __restrict__ out,
    int n_bonds)
{
    const int gwarp = (blockIdx.x * blockDim.x + threadIdx.x) >> 5;
    const int lane  = threadIdx.x & 31;

    // half-warp per bond: lanes 0-15 -> bond 2w, lanes 16-31 -> bond 2w+1
    const int b = gwarp * 2 + (lane >> 4);
    if (b >= n_bonds) return;

    const int col = (lane & 15) * 8;     // this lane's 8-float chunk

    const int2 s = __ldg(((const int2*)edge_src) + b);

    const float* a0p = atom_ft + (size_t)s.x * D + col;
    const float* a1p = atom_ft + (size_t)s.y * D + col;
    const float* bfp = bond_ft + (size_t)b   * D + col;

    // three independent 256-bit loads, all in flight together
    float v0[8], v1[8], vb[8];
    ld_v8_last (a0p, v0);
    ld_v8_last (a1p, v1);
    ld_v8_first(bfp, vb);

    float mean[8], mx[8];
#pragma unroll
    for (int i = 0; i < 8; i++) {
        mean[i] = (v0[i] + v1[i]) * 0.5f;
        mx[i]   = fmaxf(v0[i], v1[i]);
    }

    float* o = out + (size_t)b * (3 * D) + col;
    st_v4_cs(o,               vb[0],   vb[1],   vb[2],   vb[3]);
    st_v4_cs(o + 4,           vb[4],   vb[5],   vb[6],   vb[7]);
    st_v4_cs(o + D,           mean[0], mean[1], mean[2], mean[3]);
    st_v4_cs(o + D + 4,       mean[4], mean[5], mean[6], mean[7]);
    st_v4_cs(o + 2 * D,       mx[0],   mx[1],   mx[2],   mx[3]);
    st_v4_cs(o + 2 * D + 4,   mx[4],   mx[5],   mx[6],   mx[7]);
}

extern "C" void kernel_launch(void* const* d_in, const int* in_sizes, int n_in,
                              void* d_out, int out_size)
{
    const float* atom_ft  = (const float*)d_in[0];
    const float* bond_ft  = (const float*)d_in[1];
    const int*   edge_src = (const int*)d_in[2];
    // d_in[3] = edge_dst: structurally repeat(arange(n_bonds), 2); unused.

    const int n_bonds = in_sizes[1] / D;
    float* out = (float*)d_out;

    const int warps = (n_bonds + 1) >> 1;        // 2 bonds per warp
    const int warps_per_block = 256 / 32;
    const int grid = (warps + warps_per_block - 1) / warps_per_block;
    concat_mean_max_kernel<<<grid, 256>>>(atom_ft, bond_ft, edge_src, out, n_bonds);
}

// round 10
// speedup vs baseline: 1.0602x; 1.0602x over previous
#include <cuda_runtime.h>
#include <cstdint>

// ConcatenateMeanMax: out[b] = concat(bond_ft[b],
//                                     mean(atom_ft[src[2b]], atom_ft[src[2b+1]]),
//                                     max (atom_ft[src[2b]], atom_ft[src[2b+1]]))
// edge_dst = repeat(arange(N_BONDS), 2)  =>  segment b is exactly edges {2b, 2b+1}.
//
// R7 = R1 layout (one warp per bond, float4 per lane — best DRAM% at 84.4)
//    + R4 L2 policies (traffic 1.09 -> 1.03 GB), WITHOUT the 2-bond unroll
//      that serialized loads in R4 (DRAM% fell to 80.9) and WITHOUT the v8
//      loads that inflated L2 work in R5 (DRAM% fell to 77.2).
//  - atom gathers : ld.global.nc.L2::cache_hint.v4 + evict_last policy
//  - bond reads   : ld.global.nc.L2::cache_hint.v4 + evict_first policy
//  - out stores   : st.global.cs.v4

#define D 128
#define D4 (D / 4)   // 32 float4 per row == one warp

__device__ __forceinline__ float4 ldg_pol(const float4* p, uint64_t pol) {
    float4 v;
    asm("ld.global.nc.L2::cache_hint.v4.f32 {%0,%1,%2,%3}, [%4], %5;"
        : "=f"(v.x), "=f"(v.y), "=f"(v.z), "=f"(v.w) : "l"(p), "l"(pol));
    return v;
}

__device__ __forceinline__ void stg_cs(float4* p, float4 v) {
    asm volatile("st.global.cs.v4.f32 [%0], {%1,%2,%3,%4};"
                 :: "l"(p), "f"(v.x), "f"(v.y), "f"(v.z), "f"(v.w));
}

__global__ __launch_bounds__(256) void concat_mean_max_kernel(
    const float* __restrict__ atom_ft,
    const float* __restrict__ bond_ft,
    const int*   __restrict__ edge_src,
    float* __restrict__ out,
    int n_bonds)
{
    const int gwarp = (blockIdx.x * blockDim.x + threadIdx.x) >> 5;
    const int lane  = threadIdx.x & 31;
    if (gwarp >= n_bonds) return;
    const int b = gwarp;

    uint64_t pol_keep, pol_stream;
    asm("createpolicy.fractional.L2::evict_last.b64 %0, 1.0;"  : "=l"(pol_keep));
    asm("createpolicy.fractional.L2::evict_first.b64 %0, 1.0;" : "=l"(pol_stream));

    const int2 s = __ldg(((const int2*)edge_src) + b);

    const float4* a0 = (const float4*)(atom_ft + (size_t)s.x * D);
    const float4* a1 = (const float4*)(atom_ft + (size_t)s.y * D);
    const float4* bf = (const float4*)(bond_ft + (size_t)b   * D);

    // three independent 128-bit loads in flight together
    const float4 v0 = ldg_pol(a0 + lane, pol_keep);
    const float4 v1 = ldg_pol(a1 + lane, pol_keep);
    const float4 vb = ldg_pol(bf + lane, pol_stream);

    float4 mean, mx;
    mean.x = (v0.x + v1.x) * 0.5f;  mx.x = fmaxf(v0.x, v1.x);
    mean.y = (v0.y + v1.y) * 0.5f;  mx.y = fmaxf(v0.y, v1.y);
    mean.z = (v0.z + v1.z) * 0.5f;  mx.z = fmaxf(v0.z, v1.z);
    mean.w = (v0.w + v1.w) * 0.5f;  mx.w = fmaxf(v0.w, v1.w);

    float4* o = (float4*)(out + (size_t)b * (3 * D));
    stg_cs(o + lane,          vb);    // [0,128)   bond features
    stg_cs(o + D4 + lane,     mean);  // [128,256) segment mean
    stg_cs(o + 2 * D4 + lane, mx);    // [256,384) segment max
}

extern "C" void kernel_launch(void* const* d_in, const int* in_sizes, int n_in,
                              void* d_out, int out_size)
{
    const float* atom_ft  = (const float*)d_in[0];
    const float* bond_ft  = (const float*)d_in[1];
    const int*   edge_src = (const int*)d_in[2];
    // d_in[3] = edge_dst: structurally repeat(arange(n_bonds), 2); unused.

    const int n_bonds = in_sizes[1] / D;
    float* out = (float*)d_out;

    const int warps_per_block = 256 / 32;        // one bond per warp
    const int grid = (n_bonds + warps_per_block - 1) / warps_per_block;
    concat_mean_max_kernel<<<grid, 256>>>(atom_ft, bond_ft, edge_src, out, n_bonds);
}